// round 11
// baseline (speedup 1.0000x reference)
#include <cuda_runtime.h>
#include <cuda_fp16.h>
#include <math.h>
#include <stdint.h>

#define C 512
#define NC 12
#define BT 1024
#define SQ 21
#define MS 21504            // BT * 21
#define MG 12288            // BT * 12
#define EPS 1e-5f
#define BK 64
#define NCHUNK 8            // 512 / 64
#define A_TILE_B (256 * 128)            // 32768 B (256 rows x 128B, SW128)
#define B_TILE_B (128 * 128)            // 16384 B
#define STAGE_B (A_TILE_B + B_TILE_B)   // 49152 B
#define SMEM_SZ (3 * STAGE_B)           // 3-stage: 147456 B -> 1 CTA/SM

// ---------------- scratch (device globals; no allocation allowed) ----------
__device__ __half g_Hh[(size_t)4 * MS * C];    // region GEMM out (pre-BN, fp16)
__device__ __half g_Yh[(size_t)12 * MS * C];   // class GEMM out (pre-BN, fp16)
__device__ float g_hbar[(size_t)4 * BT * C];
__device__ float g_fv[(size_t)BT * NC * C];
__device__ float g_hg[(size_t)MG * C];
__device__ float g_g[(size_t)BT * NC * C];
__device__ float g_v[(size_t)BT * NC * C];
__device__ float g_rsum[4 * C], g_rsq[4 * C];
__device__ float g_csum[12 * C], g_csq[12 * C];
__device__ float g_tsum[12], g_tsq[12];

// fp16 operands
__device__ __half g_Ax[(size_t)3 * MS * C];
__device__ __half g_AH[(size_t)4 * MS * C];
__device__ __half g_fva[(size_t)MG * C];
__device__ __half g_Wt[(size_t)17 * C * C];

__constant__ int c_off3[3] = {0, 14, 28};
__constant__ int c_sel[12] = {0, 0, 0, 1, 0, 3, 2, 2, 2, 3, 3, 3};
__constant__ float c_ADJ[144] = {
    0,0,0,1,0,1,1,1,1,1,1,1,
    0,0,0,1,0,1,1,1,1,1,1,1,
    0,0,0,1,0,1,1,1,1,1,1,1,
    1,1,1,0,1,1,1,1,1,1,1,1,
    0,0,0,1,0,1,1,1,1,1,1,1,
    1,1,1,1,1,0,1,1,1,0,0,0,
    1,1,1,1,1,1,0,0,0,1,1,1,
    1,1,1,1,1,1,0,0,0,1,1,1,
    1,1,1,1,1,1,0,0,0,1,1,1,
    1,1,1,1,1,0,1,1,1,0,0,0,
    1,1,1,1,1,0,1,1,1,0,0,0,
    1,1,1,1,1,0,1,1,1,0,0,0};

// ---------------- PTX helpers ----------------------------------------------
__device__ __forceinline__ uint32_t smem_u32(const void* p) {
    uint32_t a;
    asm("{ .reg .u64 t; cvta.to.shared.u64 t, %1; cvt.u32.u64 %0, t; }"
        : "=r"(a) : "l"(p));
    return a;
}

__device__ __forceinline__ void cp16(uint32_t dst, const void* src) {
    asm volatile("cp.async.cg.shared.global [%0], [%1], 16;"
                 :: "r"(dst), "l"(src) : "memory");
}

__device__ __forceinline__ void ldm4(uint32_t* r, uint32_t addr) {
    asm volatile("ldmatrix.sync.aligned.m8n8.x4.shared.b16 {%0,%1,%2,%3}, [%4];"
                 : "=r"(r[0]), "=r"(r[1]), "=r"(r[2]), "=r"(r[3]) : "r"(addr));
}

__device__ __forceinline__ void mma16816(float* c, const uint32_t* a,
                                         const uint32_t* b) {
    asm volatile(
        "mma.sync.aligned.m16n8k16.row.col.f32.f16.f16.f32 "
        "{%0,%1,%2,%3}, {%4,%5,%6,%7}, {%8,%9}, {%0,%1,%2,%3};"
        : "+f"(c[0]), "+f"(c[1]), "+f"(c[2]), "+f"(c[3])
        : "r"(a[0]), "r"(a[1]), "r"(a[2]), "r"(a[3]), "r"(b[0]), "r"(b[1]));
}

// SW128 swizzle: 128B rows, c16 in [0,8)
__device__ __forceinline__ uint32_t sw_off(int row, int c16) {
    return (uint32_t)(row * 128 + ((c16 ^ (row & 7)) << 4));
}

// ---------------- conversion kernels ---------------------------------------
__global__ void conv_x_k(const float* __restrict__ x) {
    int m = blockIdx.x, r = blockIdx.y, tid = threadIdx.x;
    int bt = m / 21, s = m - bt * 21;
    const float* src = x + ((size_t)bt * 49 + c_off3[r] + s) * C;
    size_t dst = ((size_t)r * MS + m) * C;
#pragma unroll
    for (int h = 0; h < 2; h++) {
        int c = tid + h * 256;
        g_Ax[dst + c] = __float2half_rn(src[c]);
    }
}

// transpose weights: Wt[z][n][k] = W[z][k][n]
__global__ void conv_W_k(const float* __restrict__ rW, const float* __restrict__ cW,
                         const float* __restrict__ gW) {
    int z = blockIdx.z;
    const float* src = (z < 4) ? rW + (size_t)z * C * C
                     : (z < 16) ? cW + (size_t)(z - 4) * C * C : gW;
    __shared__ float t[32][33];
    int n0 = blockIdx.x * 32, k0 = blockIdx.y * 32;
    int tx = threadIdx.x, ty = threadIdx.y;  // 32 x 8
#pragma unroll
    for (int i = 0; i < 32; i += 8)
        t[ty + i][tx] = src[(size_t)(k0 + ty + i) * C + n0 + tx];
    __syncthreads();
#pragma unroll
    for (int i = 0; i < 32; i += 8) {
        float v = t[tx][ty + i];  // k = k0+tx, n = n0+ty+i
        size_t o = (size_t)z * C * C + (size_t)(n0 + ty + i) * C + k0 + tx;
        g_Wt[o] = __float2half_rn(v);
    }
}

// ---------------- mma.sync fp16 GEMM + fused stats ---------------------------
// CTA tile 256m x 128n, warp tile 64x64 (8 warps, 4m x 2n), BK=64, 3-stage.
// Output: fp16 (MODE 0/1) or fp32 (MODE 2). Stats from fp32 accumulators.
// MODE 0: region  MODE 1: class  MODE 2: gat
template <int MODE>
__global__ void __launch_bounds__(256, 1) mma_gemm(const float* __restrict__ bias) {
    extern __shared__ __align__(1024) char smem[];
    const uint32_t sb = smem_u32(smem);
    const int tid = threadIdx.x;
    const int wid = tid >> 5, lane = tid & 31;
    const int wm = wid >> 1, wn = wid & 1;  // 4x2 warp grid over 256x128
    const int z = blockIdx.z;
    const int m0 = blockIdx.y * 256, n0 = blockIdx.x * 128;

    const __half* Aa;
    __half* Oh = nullptr;
    float* Of = nullptr;
    int Wz;
    if (MODE == 0) {
        int s = (z < 2) ? z : 2;
        Aa = g_Ax + (size_t)s * MS * C;
        Oh = g_Hh + (size_t)z * MS * C; Wz = z;
    } else if (MODE == 1) {
        int s = c_sel[z];
        Aa = g_AH + (size_t)s * MS * C;
        Oh = g_Yh + (size_t)z * MS * C; Wz = 4 + z;
    } else {
        Aa = g_fva; Of = g_hg; Wz = 16;
    }
    const __half* Bw = g_Wt + (size_t)Wz * C * C;

    auto load_chunk = [&](int ch) {
        const uint32_t base = sb + (uint32_t)(ch % 3) * STAGE_B;
        // A: 256 rows x 8 c16
#pragma unroll
        for (int i = 0; i < 8; i++) {
            int id = tid + i * 256;              // 0..2047
            int row = id >> 3, c = id & 7;
            cp16(base + sw_off(row, c),
                 Aa + (size_t)(m0 + row) * C + ch * BK + c * 8);
        }
        // B: 128 rows x 8 c16
#pragma unroll
        for (int i = 0; i < 4; i++) {
            int id = tid + i * 256;              // 0..1023
            int row = id >> 3, c = id & 7;
            cp16(base + A_TILE_B + sw_off(row, c),
                 Bw + (size_t)(n0 + row) * C + ch * BK + c * 8);
        }
        asm volatile("cp.async.commit_group;" ::: "memory");
    };

    float acc[4][8][4];
#pragma unroll
    for (int i = 0; i < 4; i++)
#pragma unroll
        for (int j = 0; j < 8; j++)
#pragma unroll
            for (int v = 0; v < 4; v++) acc[i][j][v] = 0.f;

    load_chunk(0);
    load_chunk(1);

    for (int ch = 0; ch < NCHUNK; ch++) {
        if (ch < NCHUNK - 1)
            asm volatile("cp.async.wait_group 1;" ::: "memory");
        else
            asm volatile("cp.async.wait_group 0;" ::: "memory");
        __syncthreads();
        if (ch + 2 < NCHUNK) load_chunk(ch + 2);

        const uint32_t base = sb + (uint32_t)(ch % 3) * STAGE_B;
        const uint32_t sA = base, sB = base + A_TILE_B;

#pragma unroll
        for (int ks = 0; ks < 4; ks++) {
            uint32_t a[4][4];  // [mt]
#pragma unroll
            for (int mt = 0; mt < 4; mt++) {
                int rowa = wm * 64 + mt * 16 + (lane & 15);
                int ca = ks * 2 + (lane >> 4);
                ldm4(a[mt], sA + sw_off(rowa, ca));
            }
#pragma unroll
            for (int np = 0; np < 4; np++) {
                int rowb = wn * 64 + np * 16 + (lane & 7) + ((lane >> 4) << 3);
                int cb = ks * 2 + ((lane >> 3) & 1);
                uint32_t bb[4];
                ldm4(bb, sB + sw_off(rowb, cb));
#pragma unroll
                for (int h = 0; h < 2; h++) {
                    const int nt = np * 2 + h;
#pragma unroll
                    for (int mt = 0; mt < 4; mt++)
                        mma16816(acc[mt][nt], a[mt], &bb[h * 2]);
                }
            }
        }
    }

    // epilogue: bias add, store (fp16 for MODE 0/1), per-column partial stats
    const int rbase = m0 + wm * 64 + (lane >> 2);
    const int cbase = n0 + wn * 64 + (lane & 3) * 2;
    float ps0[8], ps1[8], qs0[8], qs1[8];
#pragma unroll
    for (int nt = 0; nt < 8; nt++) { ps0[nt] = ps1[nt] = qs0[nt] = qs1[nt] = 0.f; }

#pragma unroll
    for (int mt = 0; mt < 4; mt++)
#pragma unroll
        for (int nt = 0; nt < 8; nt++) {
            int col = cbase + nt * 8;
            float b0 = 0.f, b1 = 0.f;
            if (MODE != 2) {
                b0 = bias[z * C + col];
                b1 = bias[z * C + col + 1];
            }
            int r0 = rbase + mt * 16;
            float2 v0 = make_float2(acc[mt][nt][0] + b0, acc[mt][nt][1] + b1);
            float2 v1 = make_float2(acc[mt][nt][2] + b0, acc[mt][nt][3] + b1);
            if (MODE != 2) {
                *(__half2*)&Oh[(size_t)r0 * C + col] = __float22half2_rn(v0);
                *(__half2*)&Oh[(size_t)(r0 + 8) * C + col] = __float22half2_rn(v1);
                ps0[nt] += v0.x + v1.x;
                ps1[nt] += v0.y + v1.y;
                qs0[nt] += v0.x * v0.x + v1.x * v1.x;
                qs1[nt] += v0.y * v0.y + v1.y * v1.y;
            } else {
                *(float2*)&Of[(size_t)r0 * C + col] = v0;
                *(float2*)&Of[(size_t)(r0 + 8) * C + col] = v1;
            }
        }

    if (MODE != 2) {
        // butterfly over lanes sharing (lane & 3): xor 4, 8, 16
#pragma unroll
        for (int nt = 0; nt < 8; nt++) {
#pragma unroll
            for (int o = 4; o <= 16; o <<= 1) {
                ps0[nt] += __shfl_xor_sync(0xffffffffu, ps0[nt], o);
                ps1[nt] += __shfl_xor_sync(0xffffffffu, ps1[nt], o);
                qs0[nt] += __shfl_xor_sync(0xffffffffu, qs0[nt], o);
                qs1[nt] += __shfl_xor_sync(0xffffffffu, qs1[nt], o);
            }
        }
        __syncthreads();  // all MMAs done; smem reusable
        float* sums = (float*)smem;  // [2 arr][4 wm][128 col]
        if (lane < 4) {
#pragma unroll
            for (int nt = 0; nt < 8; nt++) {
                int col = wn * 64 + nt * 8 + lane * 2;
                sums[(0 * 4 + wm) * 128 + col + 0] = ps0[nt];
                sums[(0 * 4 + wm) * 128 + col + 1] = ps1[nt];
                sums[(1 * 4 + wm) * 128 + col + 0] = qs0[nt];
                sums[(1 * 4 + wm) * 128 + col + 1] = qs1[nt];
            }
        }
        __syncthreads();
        int arr = tid >> 7, col = tid & 127;
        float tot = sums[arr * 512 + col] + sums[arr * 512 + 128 + col] +
                    sums[arr * 512 + 256 + col] + sums[arr * 512 + 384 + col];
        float* gs;
        if (MODE == 0) gs = arr ? g_rsq : g_rsum;
        else           gs = arr ? g_csq : g_csum;
        atomicAdd(&gs[z * C + n0 + col], tot);
    }
}

// ---------------- zero stats ------------------------------------------------
__global__ void zero_stats() {
    int tid = threadIdx.x;
    for (int i = tid; i < 4 * C; i += 256) { g_rsum[i] = 0.f; g_rsq[i] = 0.f; }
    for (int i = tid; i < 12 * C; i += 256) { g_csum[i] = 0.f; g_csq[i] = 0.f; }
    if (tid < 12) { g_tsum[tid] = 0.f; g_tsq[tid] = 0.f; }
}

// ---------------- region BN apply + relu + fp16 + seq mean ------------------
__global__ void region_apply(const float* __restrict__ gamma,
                             const float* __restrict__ beta) {
    int bt = blockIdx.x, r = blockIdx.y, tid = threadIdx.x;
    const float invN = 1.f / (float)MS;
#pragma unroll
    for (int h = 0; h < 2; h++) {
        int c = tid + h * 256;
        float mean = g_rsum[r * C + c] * invN;
        float var = g_rsq[r * C + c] * invN - mean * mean;
        float inv = rsqrtf(var + EPS);
        float ga = gamma[r * C + c], be = beta[r * C + c];
        float a = 0.f;
        for (int s = 0; s < SQ; s++) {
            size_t idx = ((size_t)r * MS + bt * SQ + s) * C + c;
            float v = __half2float(g_Hh[idx]);
            v = fmaf(ga * (v - mean), inv, be);
            v = fmaxf(v, 0.f);
            g_AH[idx] = __float2half_rn(v);
            a += v;
        }
        g_hbar[((size_t)r * BT + bt) * C + c] = a * (1.f / (float)SQ);
    }
}

// ---------------- class BN apply + seq mean -> f_v (+ fp16) -----------------
__global__ void class_apply(const float* __restrict__ gamma,
                            const float* __restrict__ beta) {
    int bt = blockIdx.x, n = blockIdx.y, tid = threadIdx.x;
    const float invN = 1.f / (float)MS;
#pragma unroll
    for (int h = 0; h < 2; h++) {
        int c = tid + h * 256;
        float mean = g_csum[n * C + c] * invN;
        float var = g_csq[n * C + c] * invN - mean * mean;
        float inv = rsqrtf(var + EPS);
        float ga = gamma[n * C + c], be = beta[n * C + c];
        float a = 0.f;
        for (int s = 0; s < SQ; s++) {
            size_t idx = ((size_t)n * MS + bt * SQ + s) * C + c;
            float v = __half2float(g_Yh[idx]);
            v = fmaf(ga * (v - mean), inv, be);
            a += fmaxf(v, 0.f);
        }
        float fv = a * (1.f / (float)SQ);
        size_t o = ((size_t)bt * NC + n) * C + c;
        g_fv[o] = fv;
        g_fva[o] = __float2half_rn(fv);
    }
}

// ---------------- region head predictions ------------------------------------
__global__ void preds_kernel(const float* __restrict__ uW, const float* __restrict__ ub,
                             const float* __restrict__ mW, const float* __restrict__ mb,
                             const float* __restrict__ d1W, const float* __restrict__ d1b,
                             const float* __restrict__ d2W, const float* __restrict__ d2b,
                             float* __restrict__ out) {
    int bt = blockIdx.x, tid = threadIdx.x;  // 64 threads
    __shared__ float sh[4][C];
    for (int i = tid; i < 4 * C; i += 64)
        sh[i >> 9][i & 511] = g_hbar[((size_t)(i >> 9) * BT + bt) * C + (i & 511)];
    __syncthreads();
    if (tid < 16) {
        float s = ub[tid];
        for (int c = 0; c < C; c++) s = fmaf(sh[0][c], uW[c * 16 + tid], s);
        out[bt * 16 + tid] = s;
    } else if (tid < 18) {
        int o = tid - 16;
        float s = mb[o];
        for (int c = 0; c < C; c++) s = fmaf(sh[1][c], mW[c * 2 + o], s);
        out[16384 + bt * 2 + o] = s;
    } else if (tid < 26) {
        int o = tid - 18;
        float s = d1b[o];
        for (int c = 0; c < C; c++) s = fmaf(sh[2][c], d1W[c * 8 + o], s);
        out[18432 + bt * 8 + o] = s;
    } else if (tid < 42) {
        int o = tid - 26;
        float s = d2b[o];
        for (int c = 0; c < C; c++) s = fmaf(sh[3][c], d2W[c * 16 + o], s);
        out[26624 + bt * 16 + o] = s;
    }
}

// ---------------- GAT attention + residual -----------------------------------
__global__ void gat_attn(const float* __restrict__ adj_mask,
                         const float* __restrict__ al,
                         const float* __restrict__ ar) {
    int bt = blockIdx.x, tid = threadIdx.x;  // 256 threads
    __shared__ float shg[NC][C];
    __shared__ float sdl[NC], sdr[NC];
    __shared__ float sattn[NC][NC];

    for (int i = tid; i < NC * C; i += 256)
        shg[i >> 9][i & 511] = g_hg[((size_t)bt * NC) * C + i];
    __syncthreads();

    int warp = tid >> 5, lane = tid & 31;
    for (int job = warp; job < 24; job += 8) {
        int node = job >> 1;
        const float* vec = (job & 1) ? ar : al;
        float s = 0.f;
        for (int c = lane; c < C; c += 32) s += shg[node][c] * vec[c];
#pragma unroll
        for (int o = 16; o; o >>= 1) s += __shfl_xor_sync(0xffffffffu, s, o);
        if (lane == 0) { if (job & 1) sdr[node] = s; else sdl[node] = s; }
    }
    __syncthreads();

    if (tid < 144) {
        int i = tid / 12, j = tid - i * 12;
        float adj = c_ADJ[i * 12 + j] * adj_mask[(size_t)bt * 144 + i * 12 + j] +
                    (i == j ? 1.f : 0.f);
        float e = sdl[i] + sdr[j];
        e = (e >= 0.f) ? e : 0.2f * e;
        sattn[i][j] = (adj > 0.1f) ? e : -1e9f;
    }
    __syncthreads();

    if (tid < 12) {
        int i = tid;
        float mx = -1e30f;
        for (int j = 0; j < 12; j++) mx = fmaxf(mx, sattn[i][j]);
        float w[12];
        float sum = 0.f;
        for (int j = 0; j < 12; j++) { w[j] = expf(sattn[i][j] - mx); sum += w[j]; }
        float inv = 1.f / sum;
        for (int j = 0; j < 12; j++) sattn[i][j] = w[j] * inv;
    }
    __syncthreads();

    for (int idx = tid; idx < NC * C; idx += 256) {
        int i = idx >> 9, c = idx & 511;
        float s = 0.f;
#pragma unroll
        for (int j = 0; j < 12; j++) s = fmaf(sattn[i][j], shg[j][c], s);
        size_t o = ((size_t)bt * NC + i) * C + c;
        g_g[o] = s + g_fv[o];
    }
}

// ---------------- depthwise temporal conv + per-class stats ------------------
__global__ void tconv_kernel(const float* __restrict__ tW,
                             const float* __restrict__ tb) {
    int bt = blockIdx.x, n = blockIdx.y, tid = threadIdx.x;
    int b = bt >> 5, t = bt & 31;
    float p0 = 0.f, p1 = 0.f;
    for (int c = tid; c < C; c += 256) {
        float acc = tb[n * C + c];
#pragma unroll
        for (int k = 0; k < 5; k++) {
            int tt = t + k - 2;
            if (tt >= 0 && tt < 32)
                acc = fmaf(g_g[((size_t)(b * 32 + tt) * NC + n) * C + c],
                           tW[(n * C + c) * 5 + k], acc);
        }
        g_v[((size_t)bt * NC + n) * C + c] = acc;
        p0 += acc;
        p1 += acc * acc;
    }
    __shared__ float s0[256], s1[256];
    s0[tid] = p0; s1[tid] = p1;
    __syncthreads();
    for (int o = 128; o; o >>= 1) {
        if (tid < o) { s0[tid] += s0[tid + o]; s1[tid] += s1[tid + o]; }
        __syncthreads();
    }
    if (tid == 0) {
        atomicAdd(&g_tsum[n], s0[0]);
        atomicAdd(&g_tsq[n], s1[0]);
    }
}

__global__ void tbn_apply(const float* __restrict__ tg,
                          const float* __restrict__ tbeta,
                          float* __restrict__ out) {
    int bt = blockIdx.x, n = blockIdx.y, tid = threadIdx.x;
    const float invN = 1.f / (float)(BT * C);
    float mean = g_tsum[n] * invN;
    float var = g_tsq[n] * invN - mean * mean;
    float inv = rsqrtf(var + EPS);
    float ga = tg[n], be = tbeta[n];
    for (int c = tid; c < C; c += 256) {
        float v = g_v[((size_t)bt * NC + n) * C + c];
        v = fmaf(ga * (v - mean), inv, be);
        out[((size_t)bt * NC + n) * C + c] = fmaxf(v, 0.f);
    }
}

// ---------------- launch ------------------------------------------------------
extern "C" void kernel_launch(void* const* d_in, const int* in_sizes, int n_in,
                              void* d_out, int out_size) {
    const float* x = (const float*)d_in[0];
    const float* adj_mask = (const float*)d_in[1];
    const float* region_W = (const float*)d_in[2];
    const float* region_b = (const float*)d_in[3];
    const float* region_gamma = (const float*)d_in[4];
    const float* region_beta = (const float*)d_in[5];
    const float* upfc_W = (const float*)d_in[6];
    const float* upfc_b = (const float*)d_in[7];
    const float* midfc_W = (const float*)d_in[8];
    const float* midfc_b = (const float*)d_in[9];
    const float* d1fc_W = (const float*)d_in[10];
    const float* d1fc_b = (const float*)d_in[11];
    const float* d2fc_W = (const float*)d_in[12];
    const float* d2fc_b = (const float*)d_in[13];
    const float* class_W = (const float*)d_in[14];
    const float* class_b = (const float*)d_in[15];
    const float* class_gamma = (const float*)d_in[16];
    const float* class_beta = (const float*)d_in[17];
    const float* gat_W = (const float*)d_in[18];
    const float* gat_al = (const float*)d_in[19];
    const float* gat_ar = (const float*)d_in[20];
    const float* tconv_W = (const float*)d_in[21];
    const float* tconv_b = (const float*)d_in[22];
    const float* tbn_gamma = (const float*)d_in[23];
    const float* tbn_beta = (const float*)d_in[24];
    float* out = (float*)d_out;

    cudaFuncSetAttribute(mma_gemm<0>, cudaFuncAttributeMaxDynamicSharedMemorySize, SMEM_SZ);
    cudaFuncSetAttribute(mma_gemm<1>, cudaFuncAttributeMaxDynamicSharedMemorySize, SMEM_SZ);
    cudaFuncSetAttribute(mma_gemm<2>, cudaFuncAttributeMaxDynamicSharedMemorySize, SMEM_SZ);

    zero_stats<<<1, 256>>>();
    conv_W_k<<<dim3(16, 16, 17), dim3(32, 8)>>>(region_W, class_W, gat_W);
    conv_x_k<<<dim3(MS, 3), 256>>>(x);

    // region GEMMs: [4] x (21504 x 512 x 512), stats fused
    mma_gemm<0><<<dim3(4, 84, 4), 256, SMEM_SZ>>>(region_b);
    region_apply<<<dim3(BT, 4), 256>>>(region_gamma, region_beta);
    preds_kernel<<<BT, 64>>>(upfc_W, upfc_b, midfc_W, midfc_b,
                             d1fc_W, d1fc_b, d2fc_W, d2fc_b, out);

    // class GEMMs: [12] x (21504 x 512 x 512), stats fused
    mma_gemm<1><<<dim3(4, 84, 12), 256, SMEM_SZ>>>(class_b);
    class_apply<<<dim3(BT, 12), 256>>>(class_gamma, class_beta);

    // GAT: hg = f_v @ gat_W  (12288 x 512 x 512)
    mma_gemm<2><<<dim3(4, 48, 1), 256, SMEM_SZ>>>(nullptr);
    gat_attn<<<BT, 256>>>(adj_mask, gat_al, gat_ar);

    // temporal conv + BN
    tconv_kernel<<<dim3(BT, NC), 256>>>(tconv_W, tconv_b);
    tbn_apply<<<dim3(BT, NC), 256>>>(tbn_gamma, tbn_beta, out + 43008);
}

// round 12
// speedup vs baseline: 1.6088x; 1.6088x over previous
#include <cuda_runtime.h>
#include <cuda_fp16.h>
#include <math.h>
#include <stdint.h>

#define C 512
#define NC 12
#define BT 1024
#define SQ 21
#define MS 21504            // BT * 21
#define MG 12288            // BT * 12
#define EPS 1e-5f
#define BK 64
#define NCHUNK 8            // 512 / 64
#define TILE_B (128 * 128)              // 16384 B (128 rows x 128B, SW128)
#define STAGE_B (2 * TILE_B)            // A, B = 32768 B
#define SMEM_SZ (3 * STAGE_B)           // 3-stage: 98304 B -> 2 CTAs/SM

// ---------------- scratch (device globals; no allocation allowed) ----------
__device__ __half g_Hh[(size_t)4 * MS * C];    // region GEMM out (pre-BN, fp16)
__device__ __half g_Yh[(size_t)12 * MS * C];   // class GEMM out (pre-BN, fp16)
__device__ float g_hbar[(size_t)4 * BT * C];
__device__ float g_fv[(size_t)BT * NC * C];
__device__ float g_hg[(size_t)MG * C];
__device__ float g_g[(size_t)BT * NC * C];
__device__ float g_v[(size_t)BT * NC * C];
__device__ float g_rsum[4 * C], g_rsq[4 * C];
__device__ float g_csum[12 * C], g_csq[12 * C];
__device__ float g_tsum[12], g_tsq[12];
__device__ float g_tWt[NC * 5 * C];            // tconv_W transposed [n][k][c]

// fp16 operands
__device__ __half g_Ax[(size_t)3 * MS * C];
__device__ __half g_AH[(size_t)4 * MS * C];
__device__ __half g_fva[(size_t)MG * C];
__device__ __half g_Wt[(size_t)17 * C * C];

__constant__ int c_off3[3] = {0, 14, 28};
__constant__ int c_sel[12] = {0, 0, 0, 1, 0, 3, 2, 2, 2, 3, 3, 3};
__constant__ float c_ADJ[144] = {
    0,0,0,1,0,1,1,1,1,1,1,1,
    0,0,0,1,0,1,1,1,1,1,1,1,
    0,0,0,1,0,1,1,1,1,1,1,1,
    1,1,1,0,1,1,1,1,1,1,1,1,
    0,0,0,1,0,1,1,1,1,1,1,1,
    1,1,1,1,1,0,1,1,1,0,0,0,
    1,1,1,1,1,1,0,0,0,1,1,1,
    1,1,1,1,1,1,0,0,0,1,1,1,
    1,1,1,1,1,1,0,0,0,1,1,1,
    1,1,1,1,1,0,1,1,1,0,0,0,
    1,1,1,1,1,0,1,1,1,0,0,0,
    1,1,1,1,1,0,1,1,1,0,0,0};

// ---------------- PTX helpers ----------------------------------------------
__device__ __forceinline__ uint32_t smem_u32(const void* p) {
    uint32_t a;
    asm("{ .reg .u64 t; cvta.to.shared.u64 t, %1; cvt.u32.u64 %0, t; }"
        : "=r"(a) : "l"(p));
    return a;
}

__device__ __forceinline__ void cp16(uint32_t dst, const void* src) {
    asm volatile("cp.async.cg.shared.global [%0], [%1], 16;"
                 :: "r"(dst), "l"(src) : "memory");
}

__device__ __forceinline__ void ldm4(uint32_t* r, uint32_t addr) {
    asm volatile("ldmatrix.sync.aligned.m8n8.x4.shared.b16 {%0,%1,%2,%3}, [%4];"
                 : "=r"(r[0]), "=r"(r[1]), "=r"(r[2]), "=r"(r[3]) : "r"(addr));
}

__device__ __forceinline__ void mma16816(float* c, const uint32_t* a,
                                         const uint32_t* b) {
    asm volatile(
        "mma.sync.aligned.m16n8k16.row.col.f32.f16.f16.f32 "
        "{%0,%1,%2,%3}, {%4,%5,%6,%7}, {%8,%9}, {%0,%1,%2,%3};"
        : "+f"(c[0]), "+f"(c[1]), "+f"(c[2]), "+f"(c[3])
        : "r"(a[0]), "r"(a[1]), "r"(a[2]), "r"(a[3]), "r"(b[0]), "r"(b[1]));
}

// SW128 swizzle: 128B rows, c16 in [0,8)
__device__ __forceinline__ uint32_t sw_off(int row, int c16) {
    return (uint32_t)(row * 128 + ((c16 ^ (row & 7)) << 4));
}

// ---------------- conversion kernels ---------------------------------------
__global__ void conv_x_k(const float* __restrict__ x) {
    int m = blockIdx.x, r = blockIdx.y, tid = threadIdx.x;
    int bt = m / 21, s = m - bt * 21;
    const float* src = x + ((size_t)bt * 49 + c_off3[r] + s) * C;
    size_t dst = ((size_t)r * MS + m) * C;
    float2 v = ((const float2*)src)[tid];
    ((__half2*)&g_Ax[dst])[tid] = __float22half2_rn(v);
}

// transpose weights: Wt[z][n][k] = W[z][k][n]; block (0,0,0) also zeroes stats
__global__ void conv_W_k(const float* __restrict__ rW, const float* __restrict__ cW,
                         const float* __restrict__ gW) {
    int z = blockIdx.z;
    int tid = threadIdx.y * 32 + threadIdx.x;
    if (z == 0 && blockIdx.x == 0 && blockIdx.y == 0) {
        for (int i = tid; i < 4 * C; i += 256) { g_rsum[i] = 0.f; g_rsq[i] = 0.f; }
        for (int i = tid; i < 12 * C; i += 256) { g_csum[i] = 0.f; g_csq[i] = 0.f; }
        if (tid < 12) { g_tsum[tid] = 0.f; g_tsq[tid] = 0.f; }
    }
    const float* src = (z < 4) ? rW + (size_t)z * C * C
                     : (z < 16) ? cW + (size_t)(z - 4) * C * C : gW;
    __shared__ float t[32][33];
    int n0 = blockIdx.x * 32, k0 = blockIdx.y * 32;
    int tx = threadIdx.x, ty = threadIdx.y;  // 32 x 8
#pragma unroll
    for (int i = 0; i < 32; i += 8)
        t[ty + i][tx] = src[(size_t)(k0 + ty + i) * C + n0 + tx];
    __syncthreads();
#pragma unroll
    for (int i = 0; i < 32; i += 8) {
        float v = t[tx][ty + i];  // k = k0+tx, n = n0+ty+i
        size_t o = (size_t)z * C * C + (size_t)(n0 + ty + i) * C + k0 + tx;
        g_Wt[o] = __float2half_rn(v);
    }
}

// transpose tconv weights: g_tWt[n][k][c] = tW[(n*C+c)*5+k]
__global__ void conv_tW_k(const float* __restrict__ tW) {
    int n = blockIdx.x, tid = threadIdx.x;  // 256 threads
    for (int i = tid; i < 5 * C; i += 256) {
        int k = i / C, c = i - k * C;
        g_tWt[(n * 5 + k) * C + c] = tW[(n * C + c) * 5 + k];
    }
}

// ---------------- mma.sync fp16 GEMM + fused stats ---------------------------
// D[m][n] = sum_k A[m][k] * Wt[n][k], fp32 acc, BK=64, 3-stage cp.async.
// Output: fp16 (MODE 0/1) or fp32 (MODE 2). Stats from fp32 accumulators.
// MODE 0: region  MODE 1: class  MODE 2: gat
template <int MODE>
__global__ void __launch_bounds__(256, 2) mma_gemm(const float* __restrict__ bias) {
    extern __shared__ __align__(1024) char smem[];
    const uint32_t sb = smem_u32(smem);
    const int tid = threadIdx.x;
    const int wid = tid >> 5, lane = tid & 31;
    const int wm = wid & 3, wn = wid >> 2;  // 4x2 warp grid over 128x128
    const int z = blockIdx.z;
    const int m0 = blockIdx.y * 128, n0 = blockIdx.x * 128;

    const __half* Aa;
    __half* Oh = nullptr;
    float* Of = nullptr;
    int Wz;
    if (MODE == 0) {
        int s = (z < 2) ? z : 2;
        Aa = g_Ax + (size_t)s * MS * C;
        Oh = g_Hh + (size_t)z * MS * C; Wz = z;
    } else if (MODE == 1) {
        int s = c_sel[z];
        Aa = g_AH + (size_t)s * MS * C;
        Oh = g_Yh + (size_t)z * MS * C; Wz = 4 + z;
    } else {
        Aa = g_fva; Of = g_hg; Wz = 16;
    }
    const __half* Bw = g_Wt + (size_t)Wz * C * C;

    auto load_chunk = [&](int ch) {
        const uint32_t base = sb + (uint32_t)(ch % 3) * STAGE_B;
#pragma unroll
        for (int t = 0; t < 2; t++) {
            const __half* s = t ? Bw : Aa;
            const int r0 = t ? n0 : m0;
            const uint32_t tb = base + t * TILE_B;
#pragma unroll
            for (int i = 0; i < 4; i++) {
                int id = tid + i * 256;          // 0..1023
                int row = id >> 3, c = id & 7;
                cp16(tb + sw_off(row, c),
                     s + (size_t)(r0 + row) * C + ch * BK + c * 8);
            }
        }
        asm volatile("cp.async.commit_group;" ::: "memory");
    };

    float acc[2][8][4];
#pragma unroll
    for (int i = 0; i < 2; i++)
#pragma unroll
        for (int j = 0; j < 8; j++)
#pragma unroll
            for (int v = 0; v < 4; v++) acc[i][j][v] = 0.f;

    load_chunk(0);
    load_chunk(1);

    for (int ch = 0; ch < NCHUNK; ch++) {
        if (ch < NCHUNK - 1)
            asm volatile("cp.async.wait_group 1;" ::: "memory");
        else
            asm volatile("cp.async.wait_group 0;" ::: "memory");
        __syncthreads();
        if (ch + 2 < NCHUNK) load_chunk(ch + 2);

        const uint32_t base = sb + (uint32_t)(ch % 3) * STAGE_B;
        const uint32_t sA = base, sB = base + TILE_B;

#pragma unroll
        for (int ks = 0; ks < 4; ks++) {
            uint32_t a[2][4];  // [mt]
#pragma unroll
            for (int mt = 0; mt < 2; mt++) {
                int rowa = wm * 32 + mt * 16 + (lane & 15);
                int ca = ks * 2 + (lane >> 4);
                ldm4(a[mt], sA + sw_off(rowa, ca));
            }
#pragma unroll
            for (int np = 0; np < 4; np++) {
                int rowb = wn * 64 + np * 16 + (lane & 7) + ((lane >> 4) << 3);
                int cb = ks * 2 + ((lane >> 3) & 1);
                uint32_t bb[4];
                ldm4(bb, sB + sw_off(rowb, cb));
#pragma unroll
                for (int h = 0; h < 2; h++) {
                    const int nt = np * 2 + h;
#pragma unroll
                    for (int mt = 0; mt < 2; mt++)
                        mma16816(acc[mt][nt], a[mt], &bb[h * 2]);
                }
            }
        }
    }

    // epilogue: bias add, store (fp16 for MODE 0/1), per-column partial stats
    const int rbase = m0 + wm * 32 + (lane >> 2);
    const int cbase = n0 + wn * 64 + (lane & 3) * 2;
    float ps0[8], ps1[8], qs0[8], qs1[8];
#pragma unroll
    for (int nt = 0; nt < 8; nt++) { ps0[nt] = ps1[nt] = qs0[nt] = qs1[nt] = 0.f; }

#pragma unroll
    for (int mt = 0; mt < 2; mt++)
#pragma unroll
        for (int nt = 0; nt < 8; nt++) {
            int col = cbase + nt * 8;
            float b0 = 0.f, b1 = 0.f;
            if (MODE != 2) {
                b0 = bias[z * C + col];
                b1 = bias[z * C + col + 1];
            }
            int r0 = rbase + mt * 16;
            float2 v0 = make_float2(acc[mt][nt][0] + b0, acc[mt][nt][1] + b1);
            float2 v1 = make_float2(acc[mt][nt][2] + b0, acc[mt][nt][3] + b1);
            if (MODE != 2) {
                *(__half2*)&Oh[(size_t)r0 * C + col] = __float22half2_rn(v0);
                *(__half2*)&Oh[(size_t)(r0 + 8) * C + col] = __float22half2_rn(v1);
                ps0[nt] += v0.x + v1.x;
                ps1[nt] += v0.y + v1.y;
                qs0[nt] += v0.x * v0.x + v1.x * v1.x;
                qs1[nt] += v0.y * v0.y + v1.y * v1.y;
            } else {
                *(float2*)&Of[(size_t)r0 * C + col] = v0;
                *(float2*)&Of[(size_t)(r0 + 8) * C + col] = v1;
            }
        }

    if (MODE != 2) {
        // butterfly over lanes sharing (lane & 3): xor 4, 8, 16
#pragma unroll
        for (int nt = 0; nt < 8; nt++) {
#pragma unroll
            for (int o = 4; o <= 16; o <<= 1) {
                ps0[nt] += __shfl_xor_sync(0xffffffffu, ps0[nt], o);
                ps1[nt] += __shfl_xor_sync(0xffffffffu, ps1[nt], o);
                qs0[nt] += __shfl_xor_sync(0xffffffffu, qs0[nt], o);
                qs1[nt] += __shfl_xor_sync(0xffffffffu, qs1[nt], o);
            }
        }
        __syncthreads();  // all MMAs done; smem reusable
        float* sums = (float*)smem;  // [2 arr][4 wm][128 col]
        if (lane < 4) {
#pragma unroll
            for (int nt = 0; nt < 8; nt++) {
                int col = wn * 64 + nt * 8 + lane * 2;
                sums[(0 * 4 + wm) * 128 + col + 0] = ps0[nt];
                sums[(0 * 4 + wm) * 128 + col + 1] = ps1[nt];
                sums[(1 * 4 + wm) * 128 + col + 0] = qs0[nt];
                sums[(1 * 4 + wm) * 128 + col + 1] = qs1[nt];
            }
        }
        __syncthreads();
        int arr = tid >> 7, col = tid & 127;
        float tot = sums[arr * 512 + col] + sums[arr * 512 + 128 + col] +
                    sums[arr * 512 + 256 + col] + sums[arr * 512 + 384 + col];
        float* gs;
        if (MODE == 0) gs = arr ? g_rsq : g_rsum;
        else           gs = arr ? g_csq : g_csum;
        atomicAdd(&gs[z * C + n0 + col], tot);
    }
}

// ---------------- region BN apply + relu + fp16 + seq mean ------------------
// thread owns c pair (2*tid, 2*tid+1); half2 loads/stores
__global__ void region_apply(const float* __restrict__ gamma,
                             const float* __restrict__ beta) {
    int bt = blockIdx.x, r = blockIdx.y, tid = threadIdx.x;
    const float invN = 1.f / (float)MS;
    int c = tid * 2;
    float m0 = g_rsum[r * C + c] * invN, m1 = g_rsum[r * C + c + 1] * invN;
    float v0 = g_rsq[r * C + c] * invN - m0 * m0;
    float v1 = g_rsq[r * C + c + 1] * invN - m1 * m1;
    float i0 = rsqrtf(v0 + EPS), i1 = rsqrtf(v1 + EPS);
    float s0 = gamma[r * C + c] * i0, s1 = gamma[r * C + c + 1] * i1;
    float b0 = beta[r * C + c] - m0 * s0, b1 = beta[r * C + c + 1] - m1 * s1;
    float a0 = 0.f, a1 = 0.f;
    for (int s = 0; s < SQ; s++) {
        size_t row = ((size_t)r * MS + bt * SQ + s) * C;
        __half2 hv = *(const __half2*)&g_Hh[row + c];
        float2 f = __half22float2(hv);
        float y0 = fmaxf(fmaf(f.x, s0, b0), 0.f);
        float y1 = fmaxf(fmaf(f.y, s1, b1), 0.f);
        *(__half2*)&g_AH[row + c] = __float22half2_rn(make_float2(y0, y1));
        a0 += y0; a1 += y1;
    }
    size_t ho = ((size_t)r * BT + bt) * C + c;
    g_hbar[ho] = a0 * (1.f / (float)SQ);
    g_hbar[ho + 1] = a1 * (1.f / (float)SQ);
}

// ---------------- class BN apply + seq mean -> f_v (+ fp16) -----------------
__global__ void class_apply(const float* __restrict__ gamma,
                            const float* __restrict__ beta) {
    int bt = blockIdx.x, n = blockIdx.y, tid = threadIdx.x;
    const float invN = 1.f / (float)MS;
    int c = tid * 2;
    float m0 = g_csum[n * C + c] * invN, m1 = g_csum[n * C + c + 1] * invN;
    float v0 = g_csq[n * C + c] * invN - m0 * m0;
    float v1 = g_csq[n * C + c + 1] * invN - m1 * m1;
    float i0 = rsqrtf(v0 + EPS), i1 = rsqrtf(v1 + EPS);
    float s0 = gamma[n * C + c] * i0, s1 = gamma[n * C + c + 1] * i1;
    float b0 = beta[n * C + c] - m0 * s0, b1 = beta[n * C + c + 1] - m1 * s1;
    float a0 = 0.f, a1 = 0.f;
    for (int s = 0; s < SQ; s++) {
        size_t row = ((size_t)n * MS + bt * SQ + s) * C;
        __half2 hv = *(const __half2*)&g_Yh[row + c];
        float2 f = __half22float2(hv);
        a0 += fmaxf(fmaf(f.x, s0, b0), 0.f);
        a1 += fmaxf(fmaf(f.y, s1, b1), 0.f);
    }
    float f0 = a0 * (1.f / (float)SQ), f1 = a1 * (1.f / (float)SQ);
    size_t o = ((size_t)bt * NC + n) * C + c;
    g_fv[o] = f0; g_fv[o + 1] = f1;
    *(__half2*)&g_fva[o] = __float22half2_rn(make_float2(f0, f1));
}

// ---------------- region head predictions ------------------------------------
__global__ void preds_kernel(const float* __restrict__ uW, const float* __restrict__ ub,
                             const float* __restrict__ mW, const float* __restrict__ mb,
                             const float* __restrict__ d1W, const float* __restrict__ d1b,
                             const float* __restrict__ d2W, const float* __restrict__ d2b,
                             float* __restrict__ out) {
    int bt = blockIdx.x, tid = threadIdx.x;  // 64 threads
    __shared__ float sh[4][C];
    for (int i = tid; i < 4 * C; i += 64)
        sh[i >> 9][i & 511] = g_hbar[((size_t)(i >> 9) * BT + bt) * C + (i & 511)];
    __syncthreads();
    if (tid < 16) {
        float s = ub[tid];
        for (int c = 0; c < C; c++) s = fmaf(sh[0][c], uW[c * 16 + tid], s);
        out[bt * 16 + tid] = s;
    } else if (tid < 18) {
        int o = tid - 16;
        float s = mb[o];
        for (int c = 0; c < C; c++) s = fmaf(sh[1][c], mW[c * 2 + o], s);
        out[16384 + bt * 2 + o] = s;
    } else if (tid < 26) {
        int o = tid - 18;
        float s = d1b[o];
        for (int c = 0; c < C; c++) s = fmaf(sh[2][c], d1W[c * 8 + o], s);
        out[18432 + bt * 8 + o] = s;
    } else if (tid < 42) {
        int o = tid - 26;
        float s = d2b[o];
        for (int c = 0; c < C; c++) s = fmaf(sh[3][c], d2W[c * 16 + o], s);
        out[26624 + bt * 16 + o] = s;
    }
}

// ---------------- GAT attention + residual -----------------------------------
__global__ void gat_attn(const float* __restrict__ adj_mask,
                         const float* __restrict__ al,
                         const float* __restrict__ ar) {
    int bt = blockIdx.x, tid = threadIdx.x;  // 256 threads
    __shared__ float shg[NC][C];
    __shared__ float sdl[NC], sdr[NC];
    __shared__ float sattn[NC][NC];

    for (int i = tid; i < NC * C; i += 256)
        shg[i >> 9][i & 511] = g_hg[((size_t)bt * NC) * C + i];
    __syncthreads();

    int warp = tid >> 5, lane = tid & 31;
    for (int job = warp; job < 24; job += 8) {
        int node = job >> 1;
        const float* vec = (job & 1) ? ar : al;
        float s = 0.f;
        for (int c = lane; c < C; c += 32) s += shg[node][c] * vec[c];
#pragma unroll
        for (int o = 16; o; o >>= 1) s += __shfl_xor_sync(0xffffffffu, s, o);
        if (lane == 0) { if (job & 1) sdr[node] = s; else sdl[node] = s; }
    }
    __syncthreads();

    if (tid < 144) {
        int i = tid / 12, j = tid - i * 12;
        float adj = c_ADJ[i * 12 + j] * adj_mask[(size_t)bt * 144 + i * 12 + j] +
                    (i == j ? 1.f : 0.f);
        float e = sdl[i] + sdr[j];
        e = (e >= 0.f) ? e : 0.2f * e;
        sattn[i][j] = (adj > 0.1f) ? e : -1e9f;
    }
    __syncthreads();

    if (tid < 12) {
        int i = tid;
        float mx = -1e30f;
        for (int j = 0; j < 12; j++) mx = fmaxf(mx, sattn[i][j]);
        float w[12];
        float sum = 0.f;
        for (int j = 0; j < 12; j++) { w[j] = expf(sattn[i][j] - mx); sum += w[j]; }
        float inv = 1.f / sum;
        for (int j = 0; j < 12; j++) sattn[i][j] = w[j] * inv;
    }
    __syncthreads();

    for (int idx = tid; idx < NC * C; idx += 256) {
        int i = idx >> 9, c = idx & 511;
        float s = 0.f;
#pragma unroll
        for (int j = 0; j < 12; j++) s = fmaf(sattn[i][j], shg[j][c], s);
        size_t o = ((size_t)bt * NC + i) * C + c;
        g_g[o] = s + g_fv[o];
    }
}

// ---------------- depthwise temporal conv + per-class stats ------------------
__global__ void tconv_kernel(const float* __restrict__ tb) {
    int bt = blockIdx.x, n = blockIdx.y, tid = threadIdx.x;
    int b = bt >> 5, t = bt & 31;
    int c = tid * 2;
    float acc0 = tb[n * C + c], acc1 = tb[n * C + c + 1];
#pragma unroll
    for (int k = 0; k < 5; k++) {
        int tt = t + k - 2;
        if (tt >= 0 && tt < 32) {
            float2 gv = *(const float2*)&g_g[((size_t)(b * 32 + tt) * NC + n) * C + c];
            float2 wv = *(const float2*)&g_tWt[(n * 5 + k) * C + c];
            acc0 = fmaf(gv.x, wv.x, acc0);
            acc1 = fmaf(gv.y, wv.y, acc1);
        }
    }
    *(float2*)&g_v[((size_t)bt * NC + n) * C + c] = make_float2(acc0, acc1);
    float p0 = acc0 + acc1;
    float p1 = acc0 * acc0 + acc1 * acc1;
    __shared__ float s0[256], s1[256];
    s0[tid] = p0; s1[tid] = p1;
    __syncthreads();
    for (int o = 128; o; o >>= 1) {
        if (tid < o) { s0[tid] += s0[tid + o]; s1[tid] += s1[tid + o]; }
        __syncthreads();
    }
    if (tid == 0) {
        atomicAdd(&g_tsum[n], s0[0]);
        atomicAdd(&g_tsq[n], s1[0]);
    }
}

__global__ void tbn_apply(const float* __restrict__ tg,
                          const float* __restrict__ tbeta,
                          float* __restrict__ out) {
    int bt = blockIdx.x, n = blockIdx.y, tid = threadIdx.x;
    const float invN = 1.f / (float)(BT * C);
    float mean = g_tsum[n] * invN;
    float var = g_tsq[n] * invN - mean * mean;
    float inv = rsqrtf(var + EPS);
    float ga = tg[n] * inv, be = tbeta[n] - mean * ga;
    int c = tid * 2;
    size_t o = ((size_t)bt * NC + n) * C + c;
    float2 v = *(const float2*)&g_v[o];
    float2 r;
    r.x = fmaxf(fmaf(v.x, ga, be), 0.f);
    r.y = fmaxf(fmaf(v.y, ga, be), 0.f);
    *(float2*)&out[o] = r;
}

// ---------------- launch ------------------------------------------------------
extern "C" void kernel_launch(void* const* d_in, const int* in_sizes, int n_in,
                              void* d_out, int out_size) {
    const float* x = (const float*)d_in[0];
    const float* adj_mask = (const float*)d_in[1];
    const float* region_W = (const float*)d_in[2];
    const float* region_b = (const float*)d_in[3];
    const float* region_gamma = (const float*)d_in[4];
    const float* region_beta = (const float*)d_in[5];
    const float* upfc_W = (const float*)d_in[6];
    const float* upfc_b = (const float*)d_in[7];
    const float* midfc_W = (const float*)d_in[8];
    const float* midfc_b = (const float*)d_in[9];
    const float* d1fc_W = (const float*)d_in[10];
    const float* d1fc_b = (const float*)d_in[11];
    const float* d2fc_W = (const float*)d_in[12];
    const float* d2fc_b = (const float*)d_in[13];
    const float* class_W = (const float*)d_in[14];
    const float* class_b = (const float*)d_in[15];
    const float* class_gamma = (const float*)d_in[16];
    const float* class_beta = (const float*)d_in[17];
    const float* gat_W = (const float*)d_in[18];
    const float* gat_al = (const float*)d_in[19];
    const float* gat_ar = (const float*)d_in[20];
    const float* tconv_W = (const float*)d_in[21];
    const float* tconv_b = (const float*)d_in[22];
    const float* tbn_gamma = (const float*)d_in[23];
    const float* tbn_beta = (const float*)d_in[24];
    float* out = (float*)d_out;

    cudaFuncSetAttribute(mma_gemm<0>, cudaFuncAttributeMaxDynamicSharedMemorySize, SMEM_SZ);
    cudaFuncSetAttribute(mma_gemm<1>, cudaFuncAttributeMaxDynamicSharedMemorySize, SMEM_SZ);
    cudaFuncSetAttribute(mma_gemm<2>, cudaFuncAttributeMaxDynamicSharedMemorySize, SMEM_SZ);

    conv_W_k<<<dim3(16, 16, 17), dim3(32, 8)>>>(region_W, class_W, gat_W);
    conv_tW_k<<<NC, 256>>>(tconv_W);
    conv_x_k<<<dim3(MS, 3), 256>>>(x);

    // region GEMMs: [4] x (21504 x 512 x 512), stats fused
    mma_gemm<0><<<dim3(4, 168, 4), 256, SMEM_SZ>>>(region_b);
    region_apply<<<dim3(BT, 4), 256>>>(region_gamma, region_beta);
    preds_kernel<<<BT, 64>>>(upfc_W, upfc_b, midfc_W, midfc_b,
                             d1fc_W, d1fc_b, d2fc_W, d2fc_b, out);

    // class GEMMs: [12] x (21504 x 512 x 512), stats fused
    mma_gemm<1><<<dim3(4, 168, 12), 256, SMEM_SZ>>>(class_b);
    class_apply<<<dim3(BT, 12), 256>>>(class_gamma, class_beta);

    // GAT: hg = f_v @ gat_W  (12288 x 512 x 512)
    mma_gemm<2><<<dim3(4, 96, 1), 256, SMEM_SZ>>>(nullptr);
    gat_attn<<<BT, 256>>>(adj_mask, gat_al, gat_ar);

    // temporal conv + BN
    tconv_kernel<<<dim3(BT, NC), 256>>>(tconv_b);
    tbn_apply<<<dim3(BT, NC), 256>>>(tbn_gamma, tbn_beta, out + 43008);
}